// round 10
// baseline (speedup 1.0000x reference)
#include <cuda_runtime.h>
#include <math.h>

#define V_   100000
#define D_   128
#define B_   4096
#define NEG_ 5
#define DI_  170
#define BT_  16
#define NBLK (B_ / BT_)      // 256
#define THREADS 512
#define SQRTD 11.3137084989847604f

typedef unsigned long long u64;

__device__ __forceinline__ u64 fma2(u64 a, u64 b, u64 c) {
    u64 d;
    asm("fma.rn.f32x2 %0, %1, %2, %3;" : "=l"(d) : "l"(a), "l"(b), "l"(c));
    return d;
}
__device__ __forceinline__ u64 pk2(float lo, float hi) {
    u64 r;
    asm("mov.b64 %0, {%1, %2};" : "=l"(r) : "f"(lo), "f"(hi));
    return r;
}
__device__ __forceinline__ float2 unpk(u64 v) {
    float2 r;
    asm("mov.b64 {%0, %1}, %2;" : "=f"(r.x), "=f"(r.y) : "l"(v));
    return r;
}

// ---- device scratch ----
__device__ float g_partial[NBLK];
__device__ unsigned int g_ticket;

// ------------------------------------------------------------------
// 256 blocks x 512 threads, 16 batch rows/block, 2 blocks per SM.
//
// smem layout (bytes):
//   [0, 90624)        whg_s float4[86*65] (per-pass tile, even/odd split)
//                     / wffs float[128*177] after phase 2
//   [90624, 99328)    emb_i float4[d4*17 + slot], slot=(b&3)*4+(b>>2)
//                     / x_s float[16][128] after phase 2
//   [99328, 110208)   a_t float[170*16]
//   [110208, 110912)  inv_s float[176]
//   [110912, 110976)  wacc float[16]
//   [110976, 110980)  flag
// ------------------------------------------------------------------
#define WFF_STRIDE 177
#define OFF_EMB  90624
#define OFF_AT   99328
#define OFF_INV  110208
#define OFF_WACC 110912
#define OFF_FLAG 110976
#define SMEM_BYTES 111104

__global__ void __launch_bounds__(THREADS, 2) main_kernel(
    const int*   __restrict__ input_ids,
    const int*   __restrict__ target_ids,
    const int*   __restrict__ neg_ids,
    const float* __restrict__ W_in,
    const float* __restrict__ W_out,
    const float* __restrict__ Wh,
    const float* __restrict__ Wg,
    const float* __restrict__ Wff,
    const float* __restrict__ hs,
    const float* __restrict__ gs,
    const float* __restrict__ logit_scale,
    float*       __restrict__ out)
{
    extern __shared__ __align__(16) char smem[];
    float4* whg_s = (float4*)smem;
    float*  wffs  = (float*)smem;                    // alias after phase 2
    float4* emb_i = (float4*)(smem + OFF_EMB);
    float*  x_s   = (float*)(smem + OFF_EMB);        // alias after phase 2
    float*  a_t   = (float*)(smem + OFF_AT);
    float*  inv_s = (float*)(smem + OFF_INV);
    float*  wacc  = (float*)(smem + OFF_WACC);
    int*    sflag = (int*)(smem + OFF_FLAG);

    const int tid  = threadIdx.x;
    const int lane = tid & 31;
    const int warp = tid >> 5;                       // 0..15
    const int b0   = blockIdx.x * BT_;

    // ---- Phase 1: gather + l2-normalize 16 input embeddings (1 per warp) ----
    {
        int row = input_ids[b0 + warp];
        float4 v = ((const float4*)(W_in + (size_t)row * D_))[lane];
        float ss = v.x * v.x + v.y * v.y + v.z * v.z + v.w * v.w;
        #pragma unroll
        for (int o = 16; o; o >>= 1) ss += __shfl_xor_sync(0xffffffffu, ss, o);
        float inv = rsqrtf(ss);
        int slot = (warp & 3) * 4 + (warp >> 2);
        emb_i[lane * 17 + slot] =
            make_float4(v.x * inv, v.y * inv, v.z * inv, v.w * inv);
    }

    // ---- Prefetch phase-4 gather lines into L2 ----
    {
        int gb = b0 + warp;
        if (lane < 24) {
            int j = lane >> 2;
            int row = (j == 0) ? target_ids[gb] : neg_ids[gb * NEG_ + j - 1];
            const float* p = W_out + (size_t)row * D_ + (lane & 3) * 32;
            asm volatile("prefetch.global.L2 [%0];" :: "l"(p));
        } else if (lane < 30) {
            int j = lane - 24;
            int row = (j == 0) ? target_ids[gb] : neg_ids[gb * NEG_ + j - 1];
            const float* p = logit_scale + row;
            asm volatile("prefetch.global.L2 [%0];" :: "l"(p));
        }
    }

    // ---- Phase 2: two passes over i (86 + 84 rows) ----
    int ibase = 0;
    #pragma unroll 1
    for (int p = 0; p < 2; p++) {
        const int np    = p ? 42 : 43;     // i-pairs this pass
        const int nrows = 2 * np;

        // stage whg rows [ibase, ibase+nrows): even rows -> pos q/2,
        // odd rows -> pos np + q/2 (conflict-free paired reads later)
        #pragma unroll 1
        for (int t = warp; t < 2 * nrows; t += 16) {
            int mat = t & 1;
            int q   = t >> 1;
            int r   = ibase + q;
            int pos = (q >> 1) + (q & 1) * np;
            const float4* W = (const float4*)(mat ? Wg : Wh);
            float4 v = W[r * 32 + lane];
            float ss = v.x * v.x + v.y * v.y + v.z * v.z + v.w * v.w;
            #pragma unroll
            for (int o = 16; o; o >>= 1) ss += __shfl_xor_sync(0xffffffffu, ss, o);
            float sc = rsqrtf(ss) * (mat ? gs[r] * SQRTD : hs[r]);
            whg_s[pos * 65 + lane * 2 + mat] =
                make_float4(v.x * sc, v.y * sc, v.z * sc, v.w * sc);
        }
        __syncthreads();

        if (tid < np * 4) {
            // thread = (i-pair pp, b-quad bg): rows ibase+2pp, ibase+2pp+1
            int bg = tid & 3;
            int pp = tid >> 2;
            const ulonglong2* w0 = (const ulonglong2*)&whg_s[pp * 65];
            const ulonglong2* w1 = (const ulonglong2*)&whg_s[(np + pp) * 65];
            const ulonglong2* eb = (const ulonglong2*)emb_i;
            u64 h0[4] = {0,0,0,0}, g0[4] = {0,0,0,0};
            u64 h1[4] = {0,0,0,0}, g1[4] = {0,0,0,0};
            #pragma unroll 1
            for (int d4 = 0; d4 < 32; d4++) {
                ulonglong2 wh0 = w0[d4 * 2];
                ulonglong2 wg0 = w0[d4 * 2 + 1];
                ulonglong2 wh1 = w1[d4 * 2];
                ulonglong2 wg1 = w1[d4 * 2 + 1];
                #pragma unroll
                for (int j = 0; j < 4; j++) {
                    ulonglong2 ev = eb[d4 * 17 + j * 4 + bg];
                    h0[j] = fma2(ev.x, wh0.x, h0[j]);
                    h0[j] = fma2(ev.y, wh0.y, h0[j]);
                    g0[j] = fma2(ev.x, wg0.x, g0[j]);
                    g0[j] = fma2(ev.y, wg0.y, g0[j]);
                    h1[j] = fma2(ev.x, wh1.x, h1[j]);
                    h1[j] = fma2(ev.y, wh1.y, h1[j]);
                    g1[j] = fma2(ev.x, wg1.x, g1[j]);
                    g1[j] = fma2(ev.y, wg1.y, g1[j]);
                }
            }
            int i0 = ibase + 2 * pp;
            #pragma unroll
            for (int j = 0; j < 4; j++) {
                float2 hp = unpk(h0[j]); float2 gp = unpk(g0[j]);
                float h = hp.x + hp.y, g = gp.x + gp.y;
                a_t[i0 * 16 + bg * 4 + j] = h * (g / (1.f + __expf(-g)));
                hp = unpk(h1[j]); gp = unpk(g1[j]);
                h = hp.x + hp.y; g = gp.x + gp.y;
                a_t[(i0 + 1) * 16 + bg * 4 + j] = h * (g / (1.f + __expf(-g)));
            }
        } else if (p == 0 && tid >= 256) {
            // Wff column norms on warps 8-13 (no divergence with ph2 warps)
            int c = tid - 256;
            if (c < DI_) {
                float ss = 0.f;
                #pragma unroll 8
                for (int d = 0; d < D_; d++) {
                    float w = Wff[d * DI_ + c];     // coalesced
                    ss += w * w;
                }
                inv_s[c] = rsqrtf(ss);
            }
        }
        __syncthreads();
        ibase += nrows;
    }

    // ---- Stage wffs[d][c] = Wff[d][c] * inv[c] (pad cols 170..176 = 0) ----
    {
        #pragma unroll
        for (int rr = 0; rr < 8; rr++) {
            int d = warp * 8 + rr;
            #pragma unroll
            for (int k = 0; k < 6; k++) {
                int c = lane + 32 * k;
                if (c < DI_)
                    wffs[d * WFF_STRIDE + c] = Wff[d * DI_ + c] * inv_s[c];
                else if (c < WFF_STRIDE)
                    wffs[d * WFF_STRIDE + c] = 0.f;
            }
        }
    }
    __syncthreads();

    // ---- Phase 3: thread = d (128 threads), all 16 b, loop 170 i ----
    if (tid < 128) {
        int d = tid;
        u64 acc[8] = {0,0,0,0,0,0,0,0};
        const float* wrow = wffs + d * WFF_STRIDE;
        const ulonglong2* ap = (const ulonglong2*)a_t;
        #pragma unroll 2
        for (int i = 0; i < DI_; i++) {
            float w = wrow[i];                      // conflict-free (stride 177)
            u64 ww = pk2(w, w);
            ulonglong2 a0 = ap[i * 4 + 0];          // broadcast LDS.128
            ulonglong2 a1 = ap[i * 4 + 1];
            ulonglong2 a2 = ap[i * 4 + 2];
            ulonglong2 a3 = ap[i * 4 + 3];
            acc[0] = fma2(a0.x, ww, acc[0]);
            acc[1] = fma2(a0.y, ww, acc[1]);
            acc[2] = fma2(a1.x, ww, acc[2]);
            acc[3] = fma2(a1.y, ww, acc[3]);
            acc[4] = fma2(a2.x, ww, acc[4]);
            acc[5] = fma2(a2.y, ww, acc[5]);
            acc[6] = fma2(a3.x, ww, acc[6]);
            acc[7] = fma2(a3.y, ww, acc[7]);
        }
        #pragma unroll
        for (int k = 0; k < 8; k++) {
            float2 xp = unpk(acc[k]);
            x_s[(2 * k) * 128 + d]     = xp.x;
            x_s[(2 * k + 1) * 128 + d] = xp.y;
        }
    }

    // ---- Phase-4 gathers (x-independent; overlap ph3 on warps 4-15) ----
    float4 wv[6];
    float  lsc[6];
    {
        int gb = b0 + warp;
        int rows4[6];
        #pragma unroll
        for (int j = 0; j < 6; j++)
            rows4[j] = (j == 0) ? target_ids[gb] : neg_ids[gb * NEG_ + (j - 1)];
        #pragma unroll
        for (int j = 0; j < 6; j++)
            wv[j] = ((const float4*)(W_out + (size_t)rows4[j] * D_))[lane];
        #pragma unroll
        for (int j = 0; j < 6; j++) lsc[j] = logit_scale[rows4[j]];
    }
    __syncthreads();

    // ---- Phase 4: 6 logits per row; warp = 1 batch row ----
    float local = 0.f;
    {
        float4 x4 = ((const float4*)(x_s + warp * 128))[lane];
        #pragma unroll
        for (int j = 0; j < 6; j++) {
            float dot = wv[j].x * x4.x + wv[j].y * x4.y + wv[j].z * x4.z + wv[j].w * x4.w;
            float ss  = wv[j].x * wv[j].x + wv[j].y * wv[j].y + wv[j].z * wv[j].z + wv[j].w * wv[j].w;
            #pragma unroll
            for (int o = 16; o; o >>= 1) {
                dot += __shfl_xor_sync(0xffffffffu, dot, o);
                ss  += __shfl_xor_sync(0xffffffffu, ss, o);
            }
            if (lane == 0) {
                float logit = dot * rsqrtf(ss) * lsc[j] * SQRTD;
                float z = (j == 0) ? logit : -logit;
                float ls = fminf(z, 0.f) - log1pf(__expf(-fabsf(z)));
                local += ls * ((j == 0) ? (1.f / B_) : (1.f / (B_ * NEG_)));
            }
        }
    }
    if (lane == 0) wacc[warp] = local;
    __syncthreads();

    // ---- block partial + fused deterministic final reduction ----
    if (tid == 0) {
        float s = 0.f;
        #pragma unroll
        for (int w = 0; w < 16; w++) s += wacc[w];
        g_partial[blockIdx.x] = s;
        __threadfence();
        unsigned int t = atomicAdd(&g_ticket, 1u);
        sflag[0] = (t == NBLK - 1) ? 1 : 0;
    }
    __syncthreads();
    if (sflag[0]) {
        __threadfence();
        float* red = a_t;  // reuse smem
        if (tid < NBLK) red[tid] = g_partial[tid];
        __syncthreads();
        #pragma unroll
        for (int o = NBLK / 2; o; o >>= 1) {
            if (tid < o) red[tid] += red[tid + o];
            __syncthreads();
        }
        if (tid == 0) {
            out[0] = -red[0];
            g_ticket = 0;   // reset for next graph replay
        }
    }
}

extern "C" void kernel_launch(void* const* d_in, const int* in_sizes, int n_in,
                              void* d_out, int out_size)
{
    const int*   input_ids   = (const int*)  d_in[0];
    const int*   target_ids  = (const int*)  d_in[1];
    const int*   neg_ids     = (const int*)  d_in[2];
    const float* W_in        = (const float*)d_in[3];
    const float* W_out       = (const float*)d_in[4];
    const float* W_hidden    = (const float*)d_in[5];
    const float* W_gate      = (const float*)d_in[6];
    const float* W_ff_out    = (const float*)d_in[7];
    const float* hidden_sc   = (const float*)d_in[8];
    const float* gate_sc     = (const float*)d_in[9];
    const float* logit_scale = (const float*)d_in[10];
    float* out = (float*)d_out;

    cudaFuncSetAttribute(main_kernel, cudaFuncAttributeMaxDynamicSharedMemorySize, SMEM_BYTES);

    main_kernel<<<NBLK, THREADS, SMEM_BYTES>>>(input_ids, target_ids, neg_ids,
                                               W_in, W_out, W_hidden, W_gate,
                                               W_ff_out, hidden_sc, gate_sc,
                                               logit_scale, out);
}

// round 11
// speedup vs baseline: 1.4187x; 1.4187x over previous
#include <cuda_runtime.h>
#include <math.h>

#define V_   100000
#define D_   128
#define B_   4096
#define NEG_ 5
#define DI_  170
#define BT_  32
#define NBLK (B_ / BT_)      // 128
#define THREADS 1024
#define SQRTD 11.3137084989847604f

typedef unsigned long long u64;

__device__ __forceinline__ u64 fma2(u64 a, u64 b, u64 c) {
    u64 d;
    asm("fma.rn.f32x2 %0, %1, %2, %3;" : "=l"(d) : "l"(a), "l"(b), "l"(c));
    return d;
}
__device__ __forceinline__ u64 pk2(float lo, float hi) {
    u64 r;
    asm("mov.b64 %0, {%1, %2};" : "=l"(r) : "f"(lo), "f"(hi));
    return r;
}
__device__ __forceinline__ float2 unpk(u64 v) {
    float2 r;
    asm("mov.b64 {%0, %1}, %2;" : "=f"(r.x), "=f"(r.y) : "l"(v));
    return r;
}

// ---- device scratch ----
__device__ __align__(16) float4 g_WhgP[DI_ * 65];        // padded interleaved whg
__device__ __align__(16) float  g_WffP[D_ * 177];        // inv-prescaled Wff rows
__device__ float g_partial[NBLK];
__device__ unsigned int g_ticket;

// ------------------------------------------------------------------
// Prep: ONE normalization pass, written in main's exact smem layouts.
// grid = 170 blocks x 96 threads (3 warps): warp0 Wh row, warp1 Wg row,
// warp2 Wff column r (norm + prescale + transpose-scatter).
// ------------------------------------------------------------------
__global__ __launch_bounds__(96) void prep_kernel(
    const float* __restrict__ Wh, const float* __restrict__ Wg,
    const float* __restrict__ Wff,
    const float* __restrict__ hs, const float* __restrict__ gs)
{
    int r    = blockIdx.x;
    int mat  = threadIdx.x >> 5;
    int lane = threadIdx.x & 31;

    if (mat < 2) {
        const float4* W = (const float4*)(mat ? Wg : Wh);
        float4 v = W[r * 32 + lane];
        float ss = v.x * v.x + v.y * v.y + v.z * v.z + v.w * v.w;
        #pragma unroll
        for (int o = 16; o; o >>= 1) ss += __shfl_xor_sync(0xffffffffu, ss, o);
        float sc = rsqrtf(ss) * (mat ? gs[r] * SQRTD : hs[r]);
        g_WhgP[r * 65 + lane * 2 + mat] =
            make_float4(v.x * sc, v.y * sc, v.z * sc, v.w * sc);
    } else {
        float v[4]; float ss = 0.f;
        #pragma unroll
        for (int k = 0; k < 4; k++) {
            v[k] = Wff[(lane + 32 * k) * DI_ + r];
            ss += v[k] * v[k];
        }
        #pragma unroll
        for (int o = 16; o; o >>= 1) ss += __shfl_xor_sync(0xffffffffu, ss, o);
        float inv = rsqrtf(ss);
        #pragma unroll
        for (int k = 0; k < 4; k++)
            g_WffP[(lane + 32 * k) * 177 + r] = v[k] * inv;
        if (r < 7) {                       // zero the 7 pad columns
            #pragma unroll
            for (int k = 0; k < 4; k++)
                g_WffP[(lane + 32 * k) * 177 + DI_ + r] = 0.f;
        }
    }
}

// ------------------------------------------------------------------
// Main: 128 blocks x 1024 threads, 32 batch rows/block (R9 structure,
// weight staging replaced by bulk coalesced copies).
//
// smem layout (bytes):
//   [0, 176800)       whg_s float4[170*65]
//     after phase 2, region aliased as:
//       wffs  float[128*177]   @0      (90624)
//       xpart float[4][128*34] @90624  (69632)
//   [176800, 193184)  emb_i float4[1024]  / x_s[32][128] after phase 3
//   [193184, 215712)  a_t float[176*32]   (rows 170-175 zeroed)
//   [215712, 216416)  (spare)
//   [216416, 216544)  wacc float[32]
//   [216544, 216548)  flag
// ------------------------------------------------------------------
#define WFF_STRIDE 177
#define OFF_XPART  90624
#define XPART_IQ   4352
#define SMEM_BYTES 216576

__global__ void __launch_bounds__(THREADS) main_kernel(
    const int*   __restrict__ input_ids,
    const int*   __restrict__ target_ids,
    const int*   __restrict__ neg_ids,
    const float* __restrict__ W_in,
    const float* __restrict__ W_out,
    const float* __restrict__ logit_scale,
    float*       __restrict__ out)
{
    extern __shared__ __align__(16) char smem[];
    float4* whg_s = (float4*)smem;
    float*  wffs  = (float*)smem;                    // alias after phase 2
    float*  xpart = (float*)(smem + OFF_XPART);      // alias after phase 2
    float4* emb_i = (float4*)(smem + 176800);
    float*  x_s   = (float*)(smem + 176800);         // alias after phase 3
    float*  a_t   = (float*)(smem + 193184);
    float*  wacc  = (float*)(smem + 216416);
    int*    sflag = (int*)(smem + 216544);

    const int tid  = threadIdx.x;
    const int lane = tid & 31;
    const int warp = tid >> 5;
    const int b0   = blockIdx.x * BT_;

    // ---- Bulk copy whg (coalesced float4, L2-broadcast, deep MLP) ----
    #pragma unroll 1
    for (int f = tid; f < DI_ * 65; f += THREADS)
        whg_s[f] = g_WhgP[f];

    // ---- Phase 1: gather + l2-normalize 32 input embeddings (1 per warp) ----
    {
        int row = input_ids[b0 + warp];
        float4 v = ((const float4*)(W_in + (size_t)row * D_))[lane];
        float ss = v.x * v.x + v.y * v.y + v.z * v.z + v.w * v.w;
        #pragma unroll
        for (int o = 16; o; o >>= 1) ss += __shfl_xor_sync(0xffffffffu, ss, o);
        float inv = rsqrtf(ss);
        emb_i[lane * 32 + (warp & 3) * 8 + (warp >> 2)] =
            make_float4(v.x * inv, v.y * inv, v.z * inv, v.w * inv);
    }

    // ---- Prefetch phase-4 gather lines into L2 ----
    {
        int gb = b0 + warp;
        if (lane < 24) {
            int j = lane >> 2;
            int row = (j == 0) ? target_ids[gb] : neg_ids[gb * NEG_ + j - 1];
            const float* p = W_out + (size_t)row * D_ + (lane & 3) * 32;
            asm volatile("prefetch.global.L2 [%0];" :: "l"(p));
        } else if (lane < 30) {
            int j = lane - 24;
            int row = (j == 0) ? target_ids[gb] : neg_ids[gb * NEG_ + j - 1];
            const float* p = logit_scale + row;
            asm volatile("prefetch.global.L2 [%0];" :: "l"(p));
        }
    }
    __syncthreads();

    // ---- Phase 2: a[b][i]=silu(g)*h; thread = (i-pair, 4-b group) ----
    if (tid < 85 * 8) {
        int bg = tid & 7;
        int pp = tid >> 3;              // 0..84 -> rows i0 = 2pp, 2pp+1
        const ulonglong2* w0 = (const ulonglong2*)&whg_s[(2 * pp) * 65];
        const ulonglong2* w1 = (const ulonglong2*)&whg_s[(2 * pp + 1) * 65];
        const ulonglong2* eb = (const ulonglong2*)emb_i;
        u64 h0[4] = {0,0,0,0}, g0[4] = {0,0,0,0};
        u64 h1[4] = {0,0,0,0}, g1[4] = {0,0,0,0};
        #pragma unroll 2
        for (int d4 = 0; d4 < 32; d4++) {
            ulonglong2 wh0 = w0[d4 * 2];
            ulonglong2 wg0 = w0[d4 * 2 + 1];
            ulonglong2 wh1 = w1[d4 * 2];
            ulonglong2 wg1 = w1[d4 * 2 + 1];
            #pragma unroll
            for (int k = 0; k < 4; k++) {
                ulonglong2 ev = eb[d4 * 32 + k * 8 + bg];
                h0[k] = fma2(ev.x, wh0.x, h0[k]);
                h0[k] = fma2(ev.y, wh0.y, h0[k]);
                g0[k] = fma2(ev.x, wg0.x, g0[k]);
                g0[k] = fma2(ev.y, wg0.y, g0[k]);
                h1[k] = fma2(ev.x, wh1.x, h1[k]);
                h1[k] = fma2(ev.y, wh1.y, h1[k]);
                g1[k] = fma2(ev.x, wg1.x, g1[k]);
                g1[k] = fma2(ev.y, wg1.y, g1[k]);
            }
        }
        #pragma unroll
        for (int k = 0; k < 4; k++) {
            float2 hp = unpk(h0[k]); float2 gp = unpk(g0[k]);
            float h = hp.x + hp.y, g = gp.x + gp.y;
            a_t[(2 * pp) * 32 + 4 * bg + k] = h * (g / (1.f + __expf(-g)));
            hp = unpk(h1[k]); gp = unpk(g1[k]);
            h = hp.x + hp.y; g = gp.x + gp.y;
            a_t[(2 * pp + 1) * 32 + 4 * bg + k] = h * (g / (1.f + __expf(-g)));
        }
    } else if (tid >= 832) {                 // zero a_t pad rows (192 floats)
        a_t[DI_ * 32 + (tid - 832)] = 0.f;
    }
    __syncthreads();

    // ---- Bulk copy prescaled wffs (5664 float4, coalesced) ----
    {
        float4* dst = (float4*)wffs;
        const float4* src = (const float4*)g_WffP;
        #pragma unroll 1
        for (int f = tid; f < (D_ * WFF_STRIDE) / 4; f += THREADS)
            dst[f] = src[f];
    }
    __syncthreads();

    // ---- Phase 3: thread = (d, 16-b half, i-quarter of 44); unroll 2 ----
    {
        int d   = tid & 127;
        int grp = tid >> 7;            // 0..7
        int bg  = grp & 1;             // b half: b0 = bg*16
        int iq  = grp >> 1;            // i quarter (44 each, padded)
        int i0  = iq * 44;
        u64 acc[8] = {0,0,0,0,0,0,0,0};
        const float* wrow = wffs + d * WFF_STRIDE + i0;
        const ulonglong2* ap = (const ulonglong2*)(a_t + i0 * 32 + bg * 16);
        #pragma unroll 1
        for (int it = 0; it < 44; it += 2) {
            float wA = wrow[it];
            float wB = wrow[it + 1];
            ulonglong2 a0 = ap[0];
            ulonglong2 a1 = ap[1];
            ulonglong2 a2 = ap[2];
            ulonglong2 a3 = ap[3];
            ulonglong2 b0v = ap[8];
            ulonglong2 b1v = ap[9];
            ulonglong2 b2v = ap[10];
            ulonglong2 b3v = ap[11];
            u64 wwA = pk2(wA, wA);
            u64 wwB = pk2(wB, wB);
            acc[0] = fma2(a0.x, wwA, acc[0]);
            acc[1] = fma2(a0.y, wwA, acc[1]);
            acc[2] = fma2(a1.x, wwA, acc[2]);
            acc[3] = fma2(a1.y, wwA, acc[3]);
            acc[4] = fma2(a2.x, wwA, acc[4]);
            acc[5] = fma2(a2.y, wwA, acc[5]);
            acc[6] = fma2(a3.x, wwA, acc[6]);
            acc[7] = fma2(a3.y, wwA, acc[7]);
            acc[0] = fma2(b0v.x, wwB, acc[0]);
            acc[1] = fma2(b0v.y, wwB, acc[1]);
            acc[2] = fma2(b1v.x, wwB, acc[2]);
            acc[3] = fma2(b1v.y, wwB, acc[3]);
            acc[4] = fma2(b2v.x, wwB, acc[4]);
            acc[5] = fma2(b2v.y, wwB, acc[5]);
            acc[6] = fma2(b3v.x, wwB, acc[6]);
            acc[7] = fma2(b3v.y, wwB, acc[7]);
            ap += 16;
        }
        float* xp = xpart + iq * XPART_IQ + d * 34 + bg * 16;
        #pragma unroll
        for (int k = 0; k < 8; k++)
            *(u64*)(xp + 2 * k) = acc[k];
    }

    // ---- Phase-4 gathers (x-independent; hide under reduce) ----
    float4 wv[6];
    float  lsc[6];
    {
        int gb = b0 + warp;
        int rows4[6];
        #pragma unroll
        for (int j = 0; j < 6; j++)
            rows4[j] = (j == 0) ? target_ids[gb] : neg_ids[gb * NEG_ + (j - 1)];
        #pragma unroll
        for (int j = 0; j < 6; j++)
            wv[j] = ((const float4*)(W_out + (size_t)rows4[j] * D_))[lane];
        #pragma unroll
        for (int j = 0; j < 6; j++) lsc[j] = logit_scale[rows4[j]];
    }
    __syncthreads();

    // ---- Reduce i-quarters: x_s[b*128+d] = sum_iq xpart[iq][d*34+b] ----
    #pragma unroll
    for (int r = 0; r < 4; r++) {
        int idx = tid + r * THREADS;       // 4096 outputs
        int b = idx >> 7, d = idx & 127;
        const float* p = xpart + d * 34 + b;
        float s = p[0] + p[XPART_IQ] + p[2 * XPART_IQ] + p[3 * XPART_IQ];
        x_s[b * 128 + d] = s;
    }
    __syncthreads();

    // ---- Phase 4: 6 logits per row; warp = 1 batch row ----
    float local = 0.f;
    {
        float4 x4 = ((const float4*)(x_s + warp * 128))[lane];
        #pragma unroll
        for (int j = 0; j < 6; j++) {
            float dot = wv[j].x * x4.x + wv[j].y * x4.y + wv[j].z * x4.z + wv[j].w * x4.w;
            float ss  = wv[j].x * wv[j].x + wv[j].y * wv[j].y + wv[j].z * wv[j].z + wv[j].w * wv[j].w;
            #pragma unroll
            for (int o = 16; o; o >>= 1) {
                dot += __shfl_xor_sync(0xffffffffu, dot, o);
                ss  += __shfl_xor_sync(0xffffffffu, ss, o);
            }
            if (lane == 0) {
                float logit = dot * rsqrtf(ss) * lsc[j] * SQRTD;
                float z = (j == 0) ? logit : -logit;
                float ls = fminf(z, 0.f) - log1pf(__expf(-fabsf(z)));
                local += ls * ((j == 0) ? (1.f / B_) : (1.f / (B_ * NEG_)));
            }
        }
    }
    if (lane == 0) wacc[warp] = local;
    __syncthreads();

    // ---- block partial + fused deterministic final reduction ----
    if (tid == 0) {
        float s = 0.f;
        #pragma unroll
        for (int w = 0; w < 32; w++) s += wacc[w];
        g_partial[blockIdx.x] = s;
        __threadfence();
        unsigned int t = atomicAdd(&g_ticket, 1u);
        sflag[0] = (t == NBLK - 1) ? 1 : 0;
    }
    __syncthreads();
    if (sflag[0]) {
        __threadfence();
        float* red = a_t;  // reuse smem
        if (tid < NBLK) red[tid] = g_partial[tid];
        __syncthreads();
        #pragma unroll
        for (int o = NBLK / 2; o; o >>= 1) {
            if (tid < o) red[tid] += red[tid + o];
            __syncthreads();
        }
        if (tid == 0) {
            out[0] = -red[0];
            g_ticket = 0;   // reset for next graph replay
        }
    }
}

extern "C" void kernel_launch(void* const* d_in, const int* in_sizes, int n_in,
                              void* d_out, int out_size)
{
    const int*   input_ids   = (const int*)  d_in[0];
    const int*   target_ids  = (const int*)  d_in[1];
    const int*   neg_ids     = (const int*)  d_in[2];
    const float* W_in        = (const float*)d_in[3];
    const float* W_out       = (const float*)d_in[4];
    const float* W_hidden    = (const float*)d_in[5];
    const float* W_gate      = (const float*)d_in[6];
    const float* W_ff_out    = (const float*)d_in[7];
    const float* hidden_sc   = (const float*)d_in[8];
    const float* gate_sc     = (const float*)d_in[9];
    const float* logit_scale = (const float*)d_in[10];
    float* out = (float*)d_out;

    cudaFuncSetAttribute(main_kernel, cudaFuncAttributeMaxDynamicSharedMemorySize, SMEM_BYTES);

    prep_kernel<<<DI_, 96>>>(W_hidden, W_gate, W_ff_out, hidden_sc, gate_sc);
    main_kernel<<<NBLK, THREADS, SMEM_BYTES>>>(input_ids, target_ids, neg_ids,
                                               W_in, W_out, logit_scale, out);
}